// round 3
// baseline (speedup 1.0000x reference)
#include <cuda_runtime.h>
#include <cuda_bf16.h>
#include <stdint.h>

#define MAXN 200000
#define MAXE 3200000
#define HD   128
#define MAXFIN 192
#define MAXBLK 1024

// ---------------- scratch (device globals; no allocation allowed) ----------------
__device__ int   g_is32;
__device__ int   g_indeg[MAXN];
__device__ float g_dinv[MAXN];
__device__ int   g_rowptr[MAXN + 1];
__device__ int   g_cursor[MAXN];
__device__ int   g_col[MAXE];
__device__ int   g_src32[MAXE];
__device__ int   g_dst32[MAXE];
__device__ int   g_blockSums[MAXBLK];
__device__ int   g_blockOff[MAXBLK];
__device__ float g_bufA[(size_t)MAXN * HD];
__device__ float g_bufB[(size_t)MAXN * HD];

// ---------------- dtype detection: int64 vs int32 edge_index ----------------
__global__ void k_detect(const void* __restrict__ edge, int n) {
    if (threadIdx.x == 0 && blockIdx.x == 0) {
        const long long* e64 = (const long long*)edge;
        int is32 = 0;
        for (int i = 0; i < 64; i++) {
            long long v = e64[i];
            if (v < 0 || v >= (long long)n) { is32 = 1; break; }
        }
        g_is32 = is32;
    }
}

// ---------------- degree / edge conversion ----------------
__global__ void k_init_deg(int n) {
    int i = blockIdx.x * blockDim.x + threadIdx.x;
    if (i < n) g_indeg[i] = 0;
}

__global__ void k_count(const void* __restrict__ edge, int E, int n) {
    int e = blockIdx.x * blockDim.x + threadIdx.x;
    if (e >= E) return;
    int s, d;
    if (g_is32) {
        const int* e32 = (const int*)edge;
        s = e32[e];
        d = e32[e + E];
    } else {
        const long long* e64 = (const long long*)edge;
        s = (int)e64[e];
        d = (int)e64[e + E];
    }
    // defensive clamp: wrong ids become a visible rel_err, not a crash
    if ((unsigned)s >= (unsigned)n) s = 0;
    if ((unsigned)d >= (unsigned)n) d = 0;
    g_src32[e] = s;
    g_dst32[e] = d;
    atomicAdd(&g_indeg[d], 1);
}

__global__ void k_dinv(int n) {
    int i = blockIdx.x * blockDim.x + threadIdx.x;
    if (i < n) g_dinv[i] = rsqrtf((float)(g_indeg[i] + 1));
}

// ---------------- 3-stage exclusive scan of in-degrees -> rowptr ----------------
__global__ void k_scan1(int n) {
    __shared__ int s[256];
    int i = blockIdx.x * 256 + threadIdx.x;
    int v = (i < n) ? g_indeg[i] : 0;
    s[threadIdx.x] = v;
    __syncthreads();
    for (int off = 128; off > 0; off >>= 1) {
        if (threadIdx.x < off) s[threadIdx.x] += s[threadIdx.x + off];
        __syncthreads();
    }
    if (threadIdx.x == 0) g_blockSums[blockIdx.x] = s[0];
}

__global__ void k_scan2(int nb) {
    __shared__ int s[MAXBLK];
    int t = threadIdx.x;
    int v = (t < nb) ? g_blockSums[t] : 0;
    s[t] = v;
    __syncthreads();
    for (int off = 1; off < MAXBLK; off <<= 1) {
        int x = (t >= off) ? s[t - off] : 0;
        __syncthreads();
        s[t] += x;
        __syncthreads();
    }
    if (t < nb) g_blockOff[t] = s[t] - v;   // exclusive
}

__global__ void k_scan3(int n) {
    __shared__ int s[256];
    int t = threadIdx.x;
    int i = blockIdx.x * 256 + t;
    int v = (i < n) ? g_indeg[i] : 0;
    s[t] = v;
    __syncthreads();
    for (int off = 1; off < 256; off <<= 1) {
        int x = (t >= off) ? s[t - off] : 0;
        __syncthreads();
        s[t] += x;
        __syncthreads();
    }
    int excl = s[t] - v;
    int rp = g_blockOff[blockIdx.x] + excl;
    if (i < n) {
        g_rowptr[i] = rp;
        g_cursor[i] = rp;
        if (i == n - 1) g_rowptr[n] = rp + v;
    }
}

__global__ void k_fill(int E) {
    int e = blockIdx.x * blockDim.x + threadIdx.x;
    if (e < E) {
        int d = g_dst32[e];
        int pos = atomicAdd(&g_cursor[d], 1);
        g_col[pos] = g_src32[e];
    }
}

// ---------------- GEMM: Y[n,128] = X[n,fin] @ W[fin,128] ----------------
// grid = (ceil(n/128), 4): blockIdx.y selects a 32-col slice.
// 128 threads, each owns one row and 8 float4 accumulators (32 cols).
__global__ void k_gemm(const float* __restrict__ X, const float* __restrict__ W,
                       float* __restrict__ Y, int n, int fin) {
    __shared__ float4 Ws4[MAXFIN * 8];           // [fin][32] floats
    float* Ws = (float*)Ws4;
    const int cq = blockIdx.y;                   // col slice: [cq*32, cq*32+32)
    for (int idx = threadIdx.x; idx < fin * 32; idx += 128) {
        int k = idx >> 5, c = idx & 31;
        Ws[k * 32 + c] = W[k * HD + cq * 32 + c];
    }
    __syncthreads();

    int row = blockIdx.x * 128 + threadIdx.x;
    if (row >= n) return;

    float4 acc[8];
#pragma unroll
    for (int j = 0; j < 8; j++) acc[j] = make_float4(0.f, 0.f, 0.f, 0.f);

    const float* xp = X + (size_t)row * fin;
    for (int k = 0; k < fin; k++) {
        float xv = __ldg(xp + k);
        const float4* wr = &Ws4[k * 8];
#pragma unroll
        for (int j = 0; j < 8; j++) {
            float4 w = wr[j];
            acc[j].x = fmaf(xv, w.x, acc[j].x);
            acc[j].y = fmaf(xv, w.y, acc[j].y);
            acc[j].z = fmaf(xv, w.z, acc[j].z);
            acc[j].w = fmaf(xv, w.w, acc[j].w);
        }
    }
    float4* yp = (float4*)(Y + (size_t)row * HD + cq * 32);
#pragma unroll
    for (int j = 0; j < 8; j++) yp[j] = acc[j];
}

// ---------------- Aggregation: one warp per node, CSR gather ----------------
// out[i] = relu( dinv[i] * sum_{s in N(i)} dinv[s]*h[s] + dinv[i]^2*h[i] + bias )
__global__ void k_agg(const float* __restrict__ Hin, float* __restrict__ Hout,
                      const float* __restrict__ bias, int n, int do_relu) {
    int gt = blockIdx.x * blockDim.x + threadIdx.x;
    int node = gt >> 5;
    int lane = gt & 31;
    if (node >= n) return;

    float di = g_dinv[node];
    int s0 = g_rowptr[node];
    int s1 = g_rowptr[node + 1];

    const float4* H4 = (const float4*)Hin;
    float4 acc = make_float4(0.f, 0.f, 0.f, 0.f);

    for (int e = s0; e < s1; e++) {
        int s = __ldg(&g_col[e]);
        float cs = __ldg(&g_dinv[s]);
        float4 v = H4[(size_t)s * 32 + lane];
        acc.x = fmaf(cs, v.x, acc.x);
        acc.y = fmaf(cs, v.y, acc.y);
        acc.z = fmaf(cs, v.z, acc.z);
        acc.w = fmaf(cs, v.w, acc.w);
    }

    float4 hv = H4[(size_t)node * 32 + lane];
    float4 b4 = ((const float4*)bias)[lane];
    float dd = di * di;
    float4 r;
    r.x = fmaf(di, acc.x, fmaf(dd, hv.x, b4.x));
    r.y = fmaf(di, acc.y, fmaf(dd, hv.y, b4.y));
    r.z = fmaf(di, acc.z, fmaf(dd, hv.z, b4.z));
    r.w = fmaf(di, acc.w, fmaf(dd, hv.w, b4.w));
    if (do_relu) {
        r.x = fmaxf(r.x, 0.f); r.y = fmaxf(r.y, 0.f);
        r.z = fmaxf(r.z, 0.f); r.w = fmaxf(r.w, 0.f);
    }
    ((float4*)Hout)[(size_t)node * 32 + lane] = r;
}

// ---------------- Head: out[n,2] = H2[n,128] @ Wl[128,2] + bl ----------------
__global__ void k_head(const float* __restrict__ H2, const float* __restrict__ Wl,
                       const float* __restrict__ bl, float* __restrict__ out, int n) {
    __shared__ float wl[HD * 2];
    if (threadIdx.x < HD * 2) wl[threadIdx.x] = Wl[threadIdx.x];
    __syncthreads();
    int r = blockIdx.x * blockDim.x + threadIdx.x;
    if (r >= n) return;
    const float* h = H2 + (size_t)r * HD;
    float a0 = bl[0], a1 = bl[1];
#pragma unroll 4
    for (int k = 0; k < HD; k++) {
        float v = h[k];
        a0 = fmaf(v, wl[2 * k + 0], a0);
        a1 = fmaf(v, wl[2 * k + 1], a1);
    }
    out[2 * r + 0] = a0;
    out[2 * r + 1] = a1;
}

// ---------------- launch ----------------
extern "C" void kernel_launch(void* const* d_in, const int* in_sizes, int n_in,
                              void* d_out, int out_size) {
    const float* x   = (const float*)d_in[0];
    const void*  edge = d_in[1];
    const float* W1  = (const float*)d_in[2];
    const float* b1  = (const float*)d_in[3];
    const float* W2  = (const float*)d_in[4];
    const float* b2  = (const float*)d_in[5];
    const float* Wl  = (const float*)d_in[6];
    const float* bl  = (const float*)d_in[7];
    float* out = (float*)d_out;

    int fin = in_sizes[2] / HD;            // 165
    int n   = in_sizes[0] / fin;           // 200000
    int E   = in_sizes[1] / 2;             // 3200000

    float* bufA; float* bufB;
    cudaGetSymbolAddress((void**)&bufA, g_bufA);
    cudaGetSymbolAddress((void**)&bufB, g_bufB);

    int nb = (n + 255) / 256;              // 782 <= MAXBLK

    // dtype probe + degree + dinv + CSR build (reused for both layers)
    k_detect<<<1, 32>>>(edge, n);
    k_init_deg<<<nb, 256>>>(n);
    k_count<<<(E + 255) / 256, 256>>>(edge, E, n);
    k_dinv<<<nb, 256>>>(n);
    k_scan1<<<nb, 256>>>(n);
    k_scan2<<<1, MAXBLK>>>(nb);
    k_scan3<<<nb, 256>>>(n);
    k_fill<<<(E + 255) / 256, 256>>>(E);

    dim3 gemm_grid((n + 127) / 128, 4);

    // layer 1
    k_gemm<<<gemm_grid, 128>>>(x, W1, bufA, n, fin);
    {
        long long tot = (long long)n * 32;
        k_agg<<<(unsigned)((tot + 255) / 256), 256>>>(bufA, bufB, b1, n, 1);
    }
    // layer 2
    k_gemm<<<gemm_grid, 128>>>(bufB, W2, bufA, n, HD);
    {
        long long tot = (long long)n * 32;
        k_agg<<<(unsigned)((tot + 255) / 256), 256>>>(bufA, bufB, b2, n, 1);
    }
    // head
    k_head<<<(n + 255) / 256, 256>>>(bufB, Wl, bl, out, n);
}

// round 4
// speedup vs baseline: 1.1268x; 1.1268x over previous
#include <cuda_runtime.h>
#include <cuda_bf16.h>
#include <stdint.h>

#define MAXN 200000
#define MAXE 3200000
#define HD   128
#define MAXFIN 192
#define MAXBLK 1024

// ---------------- scratch (device globals; no allocation allowed) ----------------
__device__ int   g_is32;
__device__ int   g_indeg[MAXN];
__device__ float g_dinv[MAXN];
__device__ int   g_rowptr[MAXN + 1];
__device__ int   g_cursor[MAXN];
__device__ int   g_col[MAXE];
__device__ int   g_src32[MAXE];
__device__ int   g_dst32[MAXE];
__device__ int   g_blockSums[MAXBLK];
__device__ int   g_blockOff[MAXBLK];
__device__ float g_bufA[(size_t)MAXN * HD];
__device__ float g_bufB[(size_t)MAXN * HD];

// packed f32x2 FMA: d = a*b + d  (dual-issue fp32 path on sm_103a)
__device__ __forceinline__ void ffma2(float2& d, const float2 a, const float2 b) {
    asm("fma.rn.f32x2 %0, %1, %2, %0;"
        : "+l"(*reinterpret_cast<unsigned long long*>(&d))
        : "l"(*reinterpret_cast<const unsigned long long*>(&a)),
          "l"(*reinterpret_cast<const unsigned long long*>(&b)));
}

// ---------------- dtype detection: int64 vs int32 edge_index ----------------
__global__ void k_detect(const void* __restrict__ edge, int n) {
    if (threadIdx.x == 0 && blockIdx.x == 0) {
        const long long* e64 = (const long long*)edge;
        int is32 = 0;
        for (int i = 0; i < 64; i++) {
            long long v = e64[i];
            if (v < 0 || v >= (long long)n) { is32 = 1; break; }
        }
        g_is32 = is32;
    }
}

// ---------------- degree / edge conversion ----------------
__global__ void k_init_deg(int n) {
    int i = blockIdx.x * blockDim.x + threadIdx.x;
    if (i < n) g_indeg[i] = 0;
}

__global__ void k_count(const void* __restrict__ edge, int E, int n) {
    int e = blockIdx.x * blockDim.x + threadIdx.x;
    if (e >= E) return;
    int s, d;
    if (g_is32) {
        const int* e32 = (const int*)edge;
        s = e32[e];
        d = e32[e + E];
    } else {
        const long long* e64 = (const long long*)edge;
        s = (int)e64[e];
        d = (int)e64[e + E];
    }
    if ((unsigned)s >= (unsigned)n) s = 0;
    if ((unsigned)d >= (unsigned)n) d = 0;
    g_src32[e] = s;
    g_dst32[e] = d;
    atomicAdd(&g_indeg[d], 1);
}

__global__ void k_dinv(int n) {
    int i = blockIdx.x * blockDim.x + threadIdx.x;
    if (i < n) g_dinv[i] = rsqrtf((float)(g_indeg[i] + 1));
}

// ---------------- 3-stage exclusive scan of in-degrees -> rowptr ----------------
__global__ void k_scan1(int n) {
    __shared__ int s[256];
    int i = blockIdx.x * 256 + threadIdx.x;
    int v = (i < n) ? g_indeg[i] : 0;
    s[threadIdx.x] = v;
    __syncthreads();
    for (int off = 128; off > 0; off >>= 1) {
        if (threadIdx.x < off) s[threadIdx.x] += s[threadIdx.x + off];
        __syncthreads();
    }
    if (threadIdx.x == 0) g_blockSums[blockIdx.x] = s[0];
}

__global__ void k_scan2(int nb) {
    __shared__ int s[MAXBLK];
    int t = threadIdx.x;
    int v = (t < nb) ? g_blockSums[t] : 0;
    s[t] = v;
    __syncthreads();
    for (int off = 1; off < MAXBLK; off <<= 1) {
        int x = (t >= off) ? s[t - off] : 0;
        __syncthreads();
        s[t] += x;
        __syncthreads();
    }
    if (t < nb) g_blockOff[t] = s[t] - v;   // exclusive
}

__global__ void k_scan3(int n) {
    __shared__ int s[256];
    int t = threadIdx.x;
    int i = blockIdx.x * 256 + t;
    int v = (i < n) ? g_indeg[i] : 0;
    s[t] = v;
    __syncthreads();
    for (int off = 1; off < 256; off <<= 1) {
        int x = (t >= off) ? s[t - off] : 0;
        __syncthreads();
        s[t] += x;
        __syncthreads();
    }
    int excl = s[t] - v;
    int rp = g_blockOff[blockIdx.x] + excl;
    if (i < n) {
        g_rowptr[i] = rp;
        g_cursor[i] = rp;
        if (i == n - 1) g_rowptr[n] = rp + v;
    }
}

__global__ void k_fill(int E) {
    int e = blockIdx.x * blockDim.x + threadIdx.x;
    if (e < E) {
        int d = g_dst32[e];
        int pos = atomicAdd(&g_cursor[d], 1);
        g_col[pos] = g_src32[e];
    }
}

// ---------------- GEMM: Y[n,128] = X[n,fin] @ W[fin,128] ----------------
// grid = (ceil(n/256), 4). Block = 128 threads; each thread owns 2 rows
// (r, r+128) x one 32-col slice, accumulated as 16 f32x2 pairs per row.
// W slice staged in smem; reads are warp-broadcast (conflict-free).
__global__ void k_gemm(const float* __restrict__ X, const float* __restrict__ W,
                       float* __restrict__ Y, int n, int fin) {
    __shared__ float Ws[MAXFIN * 32];
    const int cq = blockIdx.y;                   // col slice: [cq*32, cq*32+32)
    for (int idx = threadIdx.x; idx < fin * 32; idx += 128) {
        int k = idx >> 5, c = idx & 31;
        Ws[k * 32 + c] = W[k * HD + cq * 32 + c];
    }
    __syncthreads();

    int r0 = blockIdx.x * 256 + threadIdx.x;
    int r1 = r0 + 128;
    if (r0 >= n) return;
    bool has1 = (r1 < n);

    float2 a0[16], a1[16];
#pragma unroll
    for (int j = 0; j < 16; j++) {
        a0[j] = make_float2(0.f, 0.f);
        a1[j] = make_float2(0.f, 0.f);
    }

    const float* xp0 = X + (size_t)r0 * fin;
    const float* xp1 = X + (size_t)(has1 ? r1 : r0) * fin;

    for (int k = 0; k < fin; k++) {
        float x0 = __ldg(xp0 + k);
        float x1 = __ldg(xp1 + k);
        float2 xa = make_float2(x0, x0);
        float2 xb = make_float2(x1, x1);
        const float4* wr4 = (const float4*)(Ws + k * 32);
#pragma unroll
        for (int j = 0; j < 8; j++) {
            float4 w = wr4[j];
            float2 wlo = make_float2(w.x, w.y);
            float2 whi = make_float2(w.z, w.w);
            ffma2(a0[2 * j + 0], xa, wlo);
            ffma2(a0[2 * j + 1], xa, whi);
            ffma2(a1[2 * j + 0], xb, wlo);
            ffma2(a1[2 * j + 1], xb, whi);
        }
    }

    float4* yp0 = (float4*)(Y + (size_t)r0 * HD + cq * 32);
#pragma unroll
    for (int j = 0; j < 8; j++)
        yp0[j] = make_float4(a0[2 * j].x, a0[2 * j].y, a0[2 * j + 1].x, a0[2 * j + 1].y);
    if (has1) {
        float4* yp1 = (float4*)(Y + (size_t)r1 * HD + cq * 32);
#pragma unroll
        for (int j = 0; j < 8; j++)
            yp1[j] = make_float4(a1[2 * j].x, a1[2 * j].y, a1[2 * j + 1].x, a1[2 * j + 1].y);
    }
}

// ---------------- Aggregation: one warp per node, CSR gather, unroll-4 ----------------
// out[i] = relu( dinv[i] * sum_{s in N(i)} dinv[s]*h[s] + dinv[i]^2*h[i] + bias )
__global__ void k_agg(const float* __restrict__ Hin, float* __restrict__ Hout,
                      const float* __restrict__ bias, int n, int do_relu) {
    int gt = blockIdx.x * blockDim.x + threadIdx.x;
    int node = gt >> 5;
    int lane = gt & 31;
    if (node >= n) return;

    float di = g_dinv[node];
    int s0 = g_rowptr[node];
    int s1 = g_rowptr[node + 1];

    const float4* H4 = (const float4*)Hin;
    float4 acc = make_float4(0.f, 0.f, 0.f, 0.f);
    float4 acc2 = make_float4(0.f, 0.f, 0.f, 0.f);

    int e = s0;
    for (; e + 4 <= s1; e += 4) {
        int i0 = __ldg(&g_col[e + 0]);
        int i1 = __ldg(&g_col[e + 1]);
        int i2 = __ldg(&g_col[e + 2]);
        int i3 = __ldg(&g_col[e + 3]);
        float c0 = __ldg(&g_dinv[i0]);
        float c1 = __ldg(&g_dinv[i1]);
        float c2 = __ldg(&g_dinv[i2]);
        float c3 = __ldg(&g_dinv[i3]);
        float4 v0 = H4[(size_t)i0 * 32 + lane];
        float4 v1 = H4[(size_t)i1 * 32 + lane];
        float4 v2 = H4[(size_t)i2 * 32 + lane];
        float4 v3 = H4[(size_t)i3 * 32 + lane];
        acc.x = fmaf(c0, v0.x, acc.x); acc.y = fmaf(c0, v0.y, acc.y);
        acc.z = fmaf(c0, v0.z, acc.z); acc.w = fmaf(c0, v0.w, acc.w);
        acc2.x = fmaf(c1, v1.x, acc2.x); acc2.y = fmaf(c1, v1.y, acc2.y);
        acc2.z = fmaf(c1, v1.z, acc2.z); acc2.w = fmaf(c1, v1.w, acc2.w);
        acc.x = fmaf(c2, v2.x, acc.x); acc.y = fmaf(c2, v2.y, acc.y);
        acc.z = fmaf(c2, v2.z, acc.z); acc.w = fmaf(c2, v2.w, acc.w);
        acc2.x = fmaf(c3, v3.x, acc2.x); acc2.y = fmaf(c3, v3.y, acc2.y);
        acc2.z = fmaf(c3, v3.z, acc2.z); acc2.w = fmaf(c3, v3.w, acc2.w);
    }
    for (; e < s1; e++) {
        int s = __ldg(&g_col[e]);
        float cs = __ldg(&g_dinv[s]);
        float4 v = H4[(size_t)s * 32 + lane];
        acc.x = fmaf(cs, v.x, acc.x); acc.y = fmaf(cs, v.y, acc.y);
        acc.z = fmaf(cs, v.z, acc.z); acc.w = fmaf(cs, v.w, acc.w);
    }
    acc.x += acc2.x; acc.y += acc2.y; acc.z += acc2.z; acc.w += acc2.w;

    float4 hv = H4[(size_t)node * 32 + lane];
    float4 b4 = ((const float4*)bias)[lane];
    float dd = di * di;
    float4 r;
    r.x = fmaf(di, acc.x, fmaf(dd, hv.x, b4.x));
    r.y = fmaf(di, acc.y, fmaf(dd, hv.y, b4.y));
    r.z = fmaf(di, acc.z, fmaf(dd, hv.z, b4.z));
    r.w = fmaf(di, acc.w, fmaf(dd, hv.w, b4.w));
    if (do_relu) {
        r.x = fmaxf(r.x, 0.f); r.y = fmaxf(r.y, 0.f);
        r.z = fmaxf(r.z, 0.f); r.w = fmaxf(r.w, 0.f);
    }
    ((float4*)Hout)[(size_t)node * 32 + lane] = r;
}

// ---------------- Head: out[n,2] = H2[n,128] @ Wl[128,2] + bl ----------------
__global__ void k_head(const float* __restrict__ H2, const float* __restrict__ Wl,
                       const float* __restrict__ bl, float* __restrict__ out, int n) {
    __shared__ float wl[HD * 2];
    if (threadIdx.x < HD * 2) wl[threadIdx.x] = Wl[threadIdx.x];
    __syncthreads();
    int r = blockIdx.x * blockDim.x + threadIdx.x;
    if (r >= n) return;
    const float* h = H2 + (size_t)r * HD;
    float a0 = bl[0], a1 = bl[1];
#pragma unroll 4
    for (int k = 0; k < HD; k++) {
        float v = h[k];
        a0 = fmaf(v, wl[2 * k + 0], a0);
        a1 = fmaf(v, wl[2 * k + 1], a1);
    }
    out[2 * r + 0] = a0;
    out[2 * r + 1] = a1;
}

// ---------------- launch ----------------
extern "C" void kernel_launch(void* const* d_in, const int* in_sizes, int n_in,
                              void* d_out, int out_size) {
    const float* x   = (const float*)d_in[0];
    const void*  edge = d_in[1];
    const float* W1  = (const float*)d_in[2];
    const float* b1  = (const float*)d_in[3];
    const float* W2  = (const float*)d_in[4];
    const float* b2  = (const float*)d_in[5];
    const float* Wl  = (const float*)d_in[6];
    const float* bl  = (const float*)d_in[7];
    float* out = (float*)d_out;

    int fin = in_sizes[2] / HD;            // 165
    int n   = in_sizes[0] / fin;           // 200000
    int E   = in_sizes[1] / 2;             // 3200000

    float* bufA; float* bufB;
    cudaGetSymbolAddress((void**)&bufA, g_bufA);
    cudaGetSymbolAddress((void**)&bufB, g_bufB);

    int nb = (n + 255) / 256;              // 782 <= MAXBLK

    // dtype probe + degree + dinv + CSR build (reused for both layers)
    k_detect<<<1, 32>>>(edge, n);
    k_init_deg<<<nb, 256>>>(n);
    k_count<<<(E + 255) / 256, 256>>>(edge, E, n);
    k_dinv<<<nb, 256>>>(n);
    k_scan1<<<nb, 256>>>(n);
    k_scan2<<<1, MAXBLK>>>(nb);
    k_scan3<<<nb, 256>>>(n);
    k_fill<<<(E + 255) / 256, 256>>>(E);

    dim3 gemm_grid((n + 255) / 256, 4);

    // layer 1
    k_gemm<<<gemm_grid, 128>>>(x, W1, bufA, n, fin);
    {
        long long tot = (long long)n * 32;
        k_agg<<<(unsigned)((tot + 255) / 256), 256>>>(bufA, bufB, b1, n, 1);
    }
    // layer 2
    k_gemm<<<gemm_grid, 128>>>(bufB, W2, bufA, n, HD);
    {
        long long tot = (long long)n * 32;
        k_agg<<<(unsigned)((tot + 255) / 256), 256>>>(bufA, bufB, b2, n, 1);
    }
    // head
    k_head<<<(n + 255) / 256, 256>>>(bufB, Wl, bl, out, n);
}

// round 5
// speedup vs baseline: 1.1832x; 1.0501x over previous
#include <cuda_runtime.h>
#include <cuda_bf16.h>
#include <stdint.h>

#define MAXN 200000
#define MAXE 3200000
#define HD   128
#define MAXFIN 192
#define MAXBLK 1024

// ---------------- scratch (device globals; no allocation allowed) ----------------
__device__ int   g_is32;
__device__ int   g_indeg[MAXN];
__device__ float g_dinv[MAXN];
__device__ int   g_rowptr[MAXN + 1];
__device__ int   g_cursor[MAXN];
__device__ int   g_col[MAXE];
__device__ int   g_src32[MAXE];
__device__ int   g_dst32[MAXE];
__device__ int   g_blockSums[MAXBLK];
__device__ int   g_blockOff[MAXBLK];
__device__ float g_bufA[(size_t)MAXN * HD];
__device__ float g_bufB[(size_t)MAXN * HD];

// packed f32x2 FMA: d = a*b + d  (dual-issue fp32 path on sm_103a)
__device__ __forceinline__ void ffma2(float2& d, const float2 a, const float2 b) {
    asm("fma.rn.f32x2 %0, %1, %2, %0;"
        : "+l"(*reinterpret_cast<unsigned long long*>(&d))
        : "l"(*reinterpret_cast<const unsigned long long*>(&a)),
          "l"(*reinterpret_cast<const unsigned long long*>(&b)));
}

// ---------------- dtype detection: int64 vs int32 edge_index ----------------
__global__ void k_detect(const void* __restrict__ edge, int n) {
    if (threadIdx.x == 0 && blockIdx.x == 0) {
        const long long* e64 = (const long long*)edge;
        int is32 = 0;
        for (int i = 0; i < 64; i++) {
            long long v = e64[i];
            if (v < 0 || v >= (long long)n) { is32 = 1; break; }
        }
        g_is32 = is32;
    }
}

// ---------------- degree / edge conversion ----------------
__global__ void k_init_deg(int n) {
    int i = blockIdx.x * blockDim.x + threadIdx.x;
    if (i < n) g_indeg[i] = 0;
}

__global__ void k_count(const void* __restrict__ edge, int E, int n) {
    int e = blockIdx.x * blockDim.x + threadIdx.x;
    if (e >= E) return;
    int s, d;
    if (g_is32) {
        const int* e32 = (const int*)edge;
        s = e32[e];
        d = e32[e + E];
    } else {
        const long long* e64 = (const long long*)edge;
        s = (int)e64[e];
        d = (int)e64[e + E];
    }
    if ((unsigned)s >= (unsigned)n) s = 0;
    if ((unsigned)d >= (unsigned)n) d = 0;
    g_src32[e] = s;
    g_dst32[e] = d;
    atomicAdd(&g_indeg[d], 1);
}

__global__ void k_dinv(int n) {
    int i = blockIdx.x * blockDim.x + threadIdx.x;
    if (i < n) g_dinv[i] = rsqrtf((float)(g_indeg[i] + 1));
}

// ---------------- 3-stage exclusive scan of in-degrees -> rowptr ----------------
__global__ void k_scan1(int n) {
    __shared__ int s[256];
    int i = blockIdx.x * 256 + threadIdx.x;
    int v = (i < n) ? g_indeg[i] : 0;
    s[threadIdx.x] = v;
    __syncthreads();
    for (int off = 128; off > 0; off >>= 1) {
        if (threadIdx.x < off) s[threadIdx.x] += s[threadIdx.x + off];
        __syncthreads();
    }
    if (threadIdx.x == 0) g_blockSums[blockIdx.x] = s[0];
}

__global__ void k_scan2(int nb) {
    __shared__ int s[MAXBLK];
    int t = threadIdx.x;
    int v = (t < nb) ? g_blockSums[t] : 0;
    s[t] = v;
    __syncthreads();
    for (int off = 1; off < MAXBLK; off <<= 1) {
        int x = (t >= off) ? s[t - off] : 0;
        __syncthreads();
        s[t] += x;
        __syncthreads();
    }
    if (t < nb) g_blockOff[t] = s[t] - v;   // exclusive
}

__global__ void k_scan3(int n) {
    __shared__ int s[256];
    int t = threadIdx.x;
    int i = blockIdx.x * 256 + t;
    int v = (i < n) ? g_indeg[i] : 0;
    s[t] = v;
    __syncthreads();
    for (int off = 1; off < 256; off <<= 1) {
        int x = (t >= off) ? s[t - off] : 0;
        __syncthreads();
        s[t] += x;
        __syncthreads();
    }
    int excl = s[t] - v;
    int rp = g_blockOff[blockIdx.x] + excl;
    if (i < n) {
        g_rowptr[i] = rp;
        g_cursor[i] = rp;
        if (i == n - 1) g_rowptr[n] = rp + v;
    }
}

__global__ void k_fill(int E) {
    int e = blockIdx.x * blockDim.x + threadIdx.x;
    if (e < E) {
        int d = g_dst32[e];
        int pos = atomicAdd(&g_cursor[d], 1);
        g_col[pos] = g_src32[e];
    }
}

// ---------------- GEMM: Y[n,128] = X[n,fin] @ W[fin,128] ----------------
__global__ void k_gemm(const float* __restrict__ X, const float* __restrict__ W,
                       float* __restrict__ Y, int n, int fin) {
    __shared__ float Ws[MAXFIN * 32];
    const int cq = blockIdx.y;                   // col slice: [cq*32, cq*32+32)
    for (int idx = threadIdx.x; idx < fin * 32; idx += 128) {
        int k = idx >> 5, c = idx & 31;
        Ws[k * 32 + c] = W[k * HD + cq * 32 + c];
    }
    __syncthreads();

    int r0 = blockIdx.x * 256 + threadIdx.x;
    int r1 = r0 + 128;
    if (r0 >= n) return;
    bool has1 = (r1 < n);

    float2 a0[16], a1[16];
#pragma unroll
    for (int j = 0; j < 16; j++) {
        a0[j] = make_float2(0.f, 0.f);
        a1[j] = make_float2(0.f, 0.f);
    }

    const float* xp0 = X + (size_t)r0 * fin;
    const float* xp1 = X + (size_t)(has1 ? r1 : r0) * fin;

    for (int k = 0; k < fin; k++) {
        float x0 = __ldg(xp0 + k);
        float x1 = __ldg(xp1 + k);
        float2 xa = make_float2(x0, x0);
        float2 xb = make_float2(x1, x1);
        const float4* wr4 = (const float4*)(Ws + k * 32);
#pragma unroll
        for (int j = 0; j < 8; j++) {
            float4 w = wr4[j];
            float2 wlo = make_float2(w.x, w.y);
            float2 whi = make_float2(w.z, w.w);
            ffma2(a0[2 * j + 0], xa, wlo);
            ffma2(a0[2 * j + 1], xa, whi);
            ffma2(a1[2 * j + 0], xb, wlo);
            ffma2(a1[2 * j + 1], xb, whi);
        }
    }

    float4* yp0 = (float4*)(Y + (size_t)r0 * HD + cq * 32);
#pragma unroll
    for (int j = 0; j < 8; j++)
        yp0[j] = make_float4(a0[2 * j].x, a0[2 * j].y, a0[2 * j + 1].x, a0[2 * j + 1].y);
    if (has1) {
        float4* yp1 = (float4*)(Y + (size_t)r1 * HD + cq * 32);
#pragma unroll
        for (int j = 0; j < 8; j++)
            yp1[j] = make_float4(a1[2 * j].x, a1[2 * j].y, a1[2 * j + 1].x, a1[2 * j + 1].y);
    }
}

// ---------------- Aggregation core: one warp per node, CSR gather, unroll-8 ----------------
__device__ __forceinline__ float4 agg_node(const float4* __restrict__ H4,
                                           int node, int lane, float di,
                                           const float4 b4) {
    int s0 = g_rowptr[node];
    int s1 = g_rowptr[node + 1];

    float4 acc = make_float4(0.f, 0.f, 0.f, 0.f);
    float4 acc2 = make_float4(0.f, 0.f, 0.f, 0.f);

    int e = s0;
    for (; e + 8 <= s1; e += 8) {
        int i0 = __ldg(&g_col[e + 0]);
        int i1 = __ldg(&g_col[e + 1]);
        int i2 = __ldg(&g_col[e + 2]);
        int i3 = __ldg(&g_col[e + 3]);
        int i4 = __ldg(&g_col[e + 4]);
        int i5 = __ldg(&g_col[e + 5]);
        int i6 = __ldg(&g_col[e + 6]);
        int i7 = __ldg(&g_col[e + 7]);
        float c0 = __ldg(&g_dinv[i0]);
        float c1 = __ldg(&g_dinv[i1]);
        float c2 = __ldg(&g_dinv[i2]);
        float c3 = __ldg(&g_dinv[i3]);
        float c4 = __ldg(&g_dinv[i4]);
        float c5 = __ldg(&g_dinv[i5]);
        float c6 = __ldg(&g_dinv[i6]);
        float c7 = __ldg(&g_dinv[i7]);
        float4 v0 = H4[(size_t)i0 * 32 + lane];
        float4 v1 = H4[(size_t)i1 * 32 + lane];
        float4 v2 = H4[(size_t)i2 * 32 + lane];
        float4 v3 = H4[(size_t)i3 * 32 + lane];
        float4 v4 = H4[(size_t)i4 * 32 + lane];
        float4 v5 = H4[(size_t)i5 * 32 + lane];
        float4 v6 = H4[(size_t)i6 * 32 + lane];
        float4 v7 = H4[(size_t)i7 * 32 + lane];
        acc.x = fmaf(c0, v0.x, acc.x); acc.y = fmaf(c0, v0.y, acc.y);
        acc.z = fmaf(c0, v0.z, acc.z); acc.w = fmaf(c0, v0.w, acc.w);
        acc2.x = fmaf(c1, v1.x, acc2.x); acc2.y = fmaf(c1, v1.y, acc2.y);
        acc2.z = fmaf(c1, v1.z, acc2.z); acc2.w = fmaf(c1, v1.w, acc2.w);
        acc.x = fmaf(c2, v2.x, acc.x); acc.y = fmaf(c2, v2.y, acc.y);
        acc.z = fmaf(c2, v2.z, acc.z); acc.w = fmaf(c2, v2.w, acc.w);
        acc2.x = fmaf(c3, v3.x, acc2.x); acc2.y = fmaf(c3, v3.y, acc2.y);
        acc2.z = fmaf(c3, v3.z, acc2.z); acc2.w = fmaf(c3, v3.w, acc2.w);
        acc.x = fmaf(c4, v4.x, acc.x); acc.y = fmaf(c4, v4.y, acc.y);
        acc.z = fmaf(c4, v4.z, acc.z); acc.w = fmaf(c4, v4.w, acc.w);
        acc2.x = fmaf(c5, v5.x, acc2.x); acc2.y = fmaf(c5, v5.y, acc2.y);
        acc2.z = fmaf(c5, v5.z, acc2.z); acc2.w = fmaf(c5, v5.w, acc2.w);
        acc.x = fmaf(c6, v6.x, acc.x); acc.y = fmaf(c6, v6.y, acc.y);
        acc.z = fmaf(c6, v6.z, acc.z); acc.w = fmaf(c6, v6.w, acc.w);
        acc2.x = fmaf(c7, v7.x, acc2.x); acc2.y = fmaf(c7, v7.y, acc2.y);
        acc2.z = fmaf(c7, v7.z, acc2.z); acc2.w = fmaf(c7, v7.w, acc2.w);
    }
    for (; e < s1; e++) {
        int s = __ldg(&g_col[e]);
        float cs = __ldg(&g_dinv[s]);
        float4 v = H4[(size_t)s * 32 + lane];
        acc.x = fmaf(cs, v.x, acc.x); acc.y = fmaf(cs, v.y, acc.y);
        acc.z = fmaf(cs, v.z, acc.z); acc.w = fmaf(cs, v.w, acc.w);
    }
    acc.x += acc2.x; acc.y += acc2.y; acc.z += acc2.z; acc.w += acc2.w;

    float4 hv = H4[(size_t)node * 32 + lane];
    float dd = di * di;
    float4 r;
    r.x = fmaf(di, acc.x, fmaf(dd, hv.x, b4.x));
    r.y = fmaf(di, acc.y, fmaf(dd, hv.y, b4.y));
    r.z = fmaf(di, acc.z, fmaf(dd, hv.z, b4.z));
    r.w = fmaf(di, acc.w, fmaf(dd, hv.w, b4.w));
    r.x = fmaxf(r.x, 0.f); r.y = fmaxf(r.y, 0.f);
    r.z = fmaxf(r.z, 0.f); r.w = fmaxf(r.w, 0.f);
    return r;
}

// layer-1 aggregation: write full relu(h) row
__global__ void k_agg(const float* __restrict__ Hin, float* __restrict__ Hout,
                      const float* __restrict__ bias, int n) {
    int gt = blockIdx.x * blockDim.x + threadIdx.x;
    int node = gt >> 5;
    int lane = gt & 31;
    if (node >= n) return;
    float di = g_dinv[node];
    float4 b4 = ((const float4*)bias)[lane];
    float4 r = agg_node((const float4*)Hin, node, lane, di, b4);
    ((float4*)Hout)[(size_t)node * 32 + lane] = r;
}

// layer-2 aggregation fused with the linear head: write out[n,2] only
__global__ void k_agg_head(const float* __restrict__ Hin,
                           const float* __restrict__ bias,
                           const float* __restrict__ Wl,
                           const float* __restrict__ bl,
                           float* __restrict__ out, int n) {
    int gt = blockIdx.x * blockDim.x + threadIdx.x;
    int node = gt >> 5;
    int lane = gt & 31;
    if (node >= n) return;
    float di = g_dinv[node];
    float4 b4 = ((const float4*)bias)[lane];
    float4 r = agg_node((const float4*)Hin, node, lane, di, b4);

    // head: lane covers cols 4*lane .. 4*lane+3
    const float4* Wl4 = (const float4*)Wl;
    float4 w01 = __ldg(&Wl4[2 * lane + 0]);  // {W[4l][0],W[4l][1],W[4l+1][0],W[4l+1][1]}
    float4 w23 = __ldg(&Wl4[2 * lane + 1]);
    float a0 = r.x * w01.x + r.y * w01.z + r.z * w23.x + r.w * w23.z;
    float a1 = r.x * w01.y + r.y * w01.w + r.z * w23.y + r.w * w23.w;
#pragma unroll
    for (int off = 16; off > 0; off >>= 1) {
        a0 += __shfl_down_sync(0xffffffffu, a0, off);
        a1 += __shfl_down_sync(0xffffffffu, a1, off);
    }
    if (lane == 0) {
        out[2 * node + 0] = a0 + __ldg(&bl[0]);
        out[2 * node + 1] = a1 + __ldg(&bl[1]);
    }
}

// ---------------- launch ----------------
extern "C" void kernel_launch(void* const* d_in, const int* in_sizes, int n_in,
                              void* d_out, int out_size) {
    const float* x   = (const float*)d_in[0];
    const void*  edge = d_in[1];
    const float* W1  = (const float*)d_in[2];
    const float* b1  = (const float*)d_in[3];
    const float* W2  = (const float*)d_in[4];
    const float* b2  = (const float*)d_in[5];
    const float* Wl  = (const float*)d_in[6];
    const float* bl  = (const float*)d_in[7];
    float* out = (float*)d_out;

    int fin = in_sizes[2] / HD;            // 165
    int n   = in_sizes[0] / fin;           // 200000
    int E   = in_sizes[1] / 2;             // 3200000

    float* bufA; float* bufB;
    cudaGetSymbolAddress((void**)&bufA, g_bufA);
    cudaGetSymbolAddress((void**)&bufB, g_bufB);

    int nb = (n + 255) / 256;              // 782 <= MAXBLK
    dim3 gemm_grid((n + 255) / 256, 4);

    // launch order arranged so the heavy k_gemm sits at the slot ncu's
    // fixed -s/-c window captures (was k_dinv in rounds 3/4).
    k_detect<<<1, 32>>>(edge, n);
    k_init_deg<<<nb, 256>>>(n);
    k_count<<<(E + 255) / 256, 256>>>(edge, E, n);

    k_gemm<<<gemm_grid, 128>>>(x, W1, bufA, n, fin);   // layer-1 GEMM (indep of CSR)

    k_dinv<<<nb, 256>>>(n);
    k_scan1<<<nb, 256>>>(n);
    k_scan2<<<1, MAXBLK>>>(nb);
    k_scan3<<<nb, 256>>>(n);
    k_fill<<<(E + 255) / 256, 256>>>(E);

    long long tot = (long long)n * 32;
    k_agg<<<(unsigned)((tot + 255) / 256), 256>>>(bufA, bufB, b1, n);
    k_gemm<<<gemm_grid, 128>>>(bufB, W2, bufA, n, HD);
    k_agg_head<<<(unsigned)((tot + 255) / 256), 256>>>(bufA, b2, Wl, bl, out, n);
}